// round 2
// baseline (speedup 1.0000x reference)
#include <cuda_runtime.h>
#include <cuda_bf16.h>
#include <cstdint>

// ============================================================================
// S4D: K[i] = C @ A^i @ B, A diagonal.
//   K[i][m][d] = sum_n C[m][n] * a_n^i * B[n][d]
//   => GEMM: K[4096, 16384] = V[4096, 64] @ W[64, 16384]
//      V[i][n] = a_n^i,  W[n][m*128+d] = C[m][n]*B[n][d]
// Harness PTX target is sm_103 (generic) -> no tcgen05. Use mma.sync bf16
// (HMMA) with bf16x3 error-compensated split for fp32-grade accuracy.
// ============================================================================

#define L_LEN 4096
#define NS 64
#define DM 128
#define COLS_TOTAL (DM * DM)   // 16384

// -------- scratch (device globals: no allocation allowed) --------
__device__ __nv_bfloat16 g_Vhi[L_LEN * NS];
__device__ __nv_bfloat16 g_Vlo[L_LEN * NS];
__device__ __nv_bfloat16 g_Whi[COLS_TOTAL * NS];
__device__ __nv_bfloat16 g_Wlo[COLS_TOTAL * NS];

// -------- SMEM layout: 4 tiles of 128 rows x 64 bf16 (128B rows, swizzled) --
#define SM_A_HI 0
#define SM_A_LO 16384
#define SM_B_HI 32768
#define SM_B_LO 49152
#define SMEM_TOTAL 65536

__device__ __forceinline__ uint32_t smem_u32(const void* p) {
    uint32_t a;
    asm("{ .reg .u64 t; cvta.to.shared.u64 t, %1; cvt.u32.u64 %0, t; }"
        : "=r"(a) : "l"(p));
    return a;
}

// row-XOR swizzle: 16B chunk index c -> c ^ (row & 7). Conflict-free for
// 128B-stride rows on both STS.128 fills and LDSM row gathers.
__device__ __forceinline__ uint32_t swz_addr(uint32_t base, int row, int chunk) {
    return base + (uint32_t)row * 128u + (uint32_t)((chunk ^ (row & 7)) * 16);
}

__device__ __forceinline__ void ldsm_x4(uint32_t addr, uint32_t& r0, uint32_t& r1,
                                        uint32_t& r2, uint32_t& r3) {
    asm volatile("ldmatrix.sync.aligned.m8n8.x4.shared.b16 {%0,%1,%2,%3}, [%4];"
                 : "=r"(r0), "=r"(r1), "=r"(r2), "=r"(r3) : "r"(addr));
}

__device__ __forceinline__ void mma_16816(float* c, const uint32_t* a,
                                          const uint32_t* b) {
    asm volatile(
        "mma.sync.aligned.m16n8k16.row.col.f32.bf16.bf16.f32 "
        "{%0,%1,%2,%3}, {%4,%5,%6,%7}, {%8,%9}, {%0,%1,%2,%3};"
        : "+f"(c[0]), "+f"(c[1]), "+f"(c[2]), "+f"(c[3])
        : "r"(a[0]), "r"(a[1]), "r"(a[2]), "r"(a[3]), "r"(b[0]), "r"(b[1]));
}

// ============================================================================
// Prep 1: V[i][n] = a_n^i in fp64, split to bf16 hi/lo.
// ============================================================================
__global__ void s4d_prep_v(const float* __restrict__ A) {
    int idx = blockIdx.x * blockDim.x + threadIdx.x;
    if (idx >= L_LEN * NS) return;
    int i = idx >> 6;
    int n = idx & 63;
    float a = A[n * NS + n];  // diagonal entry
    double v;
    if (a > 0.0f)      v = exp((double)i * log((double)a));
    else               v = (i == 0) ? 1.0 : 0.0;
    float vf = (float)v;
    __nv_bfloat16 hi = __float2bfloat16(vf);
    float lo = vf - __bfloat162float(hi);
    g_Vhi[idx] = hi;
    g_Vlo[idx] = __float2bfloat16(lo);
}

// ============================================================================
// Prep 2: W[col][n] = C[m][n]*B[n][d], col = m*128+d. K-major rows (64 n's).
// ============================================================================
__global__ void s4d_prep_w(const float* __restrict__ C, const float* __restrict__ Bm) {
    int idx = blockIdx.x * blockDim.x + threadIdx.x;
    if (idx >= COLS_TOTAL * NS) return;
    int col = idx >> 6;
    int n = idx & 63;
    int m = col >> 7;
    int d = col & 127;
    float w = C[m * NS + n] * Bm[n * DM + d];
    __nv_bfloat16 hi = __float2bfloat16(w);
    float lo = w - __bfloat162float(hi);
    g_Whi[idx] = hi;
    g_Wlo[idx] = __float2bfloat16(lo);
}

// ============================================================================
// Main: CTA = 128(i) x 128(col), 8 warps of 64x32. 3 passes x 4 k-steps of
// m16n8k16 bf16 mma.sync; direct float2 stores (full 32B sectors).
// ============================================================================
__global__ void __launch_bounds__(256, 2) s4d_mma_kernel(float* __restrict__ out) {
    extern __shared__ char smem[];
    const uint32_t sb = smem_u32(smem);
    const int tid  = threadIdx.x;
    const int wid  = tid >> 5;
    const int lane = tid & 31;
    const int c0 = blockIdx.x * 128;   // output-column tile
    const int i0 = blockIdx.y * 128;   // i-row tile

    // ---- fill 4 SMEM tiles (each 128 rows x 8 x 16B chunks, swizzled) ----
    {
        const uint4* vhi = (const uint4*)g_Vhi;
        const uint4* vlo = (const uint4*)g_Vlo;
        const uint4* whi = (const uint4*)g_Whi;
        const uint4* wlo = (const uint4*)g_Wlo;
        uint4* s = (uint4*)smem;
#pragma unroll
        for (int j = 0; j < 4; j++) {
            int idx = tid + j * 256;          // 1024 chunks per tile
            int r  = idx >> 3;
            int ch = idx & 7;
            int cs = ch ^ (r & 7);
            int so = r * 8 + cs;
            s[(SM_A_HI >> 4) + so] = vhi[(size_t)(i0 + r) * 8 + ch];
            s[(SM_A_LO >> 4) + so] = vlo[(size_t)(i0 + r) * 8 + ch];
            s[(SM_B_HI >> 4) + so] = whi[(size_t)(c0 + r) * 8 + ch];
            s[(SM_B_LO >> 4) + so] = wlo[(size_t)(c0 + r) * 8 + ch];
        }
    }
    __syncthreads();

    // ---- warp tiling: warp w covers rows m_w..m_w+63, cols n_w..n_w+31 ----
    const int m_w = (wid & 1) * 64;
    const int n_w = (wid >> 1) * 32;

    float c[4][4][4];
#pragma unroll
    for (int mi = 0; mi < 4; mi++)
#pragma unroll
        for (int ni = 0; ni < 4; ni++)
#pragma unroll
            for (int k = 0; k < 4; k++) c[mi][ni][k] = 0.0f;

    // ldmatrix row/chunk components (per lane, base-relative)
    const int a_row_l = (lane & 7) + ((lane >> 3) & 1) * 8;   // within 16-row tile
    const int a_chk_l = (lane >> 4);                          // 0 or 1
    const int b_row_l = (lane & 7) + ((lane >> 4) & 1) * 8;   // within 16-n pair
    const int b_chk_l = (lane >> 3) & 1;

#pragma unroll
    for (int pass = 0; pass < 3; pass++) {
        const uint32_t abase = sb + (pass == 2 ? SM_A_LO : SM_A_HI);
        const uint32_t bbase = sb + (pass == 1 ? SM_B_LO : SM_B_HI);
#pragma unroll
        for (int ks = 0; ks < 4; ks++) {
            uint32_t a[4][4];
#pragma unroll
            for (int mi = 0; mi < 4; mi++) {
                int row = m_w + mi * 16 + a_row_l;
                ldsm_x4(swz_addr(abase, row, ks * 2 + a_chk_l),
                        a[mi][0], a[mi][1], a[mi][2], a[mi][3]);
            }
            uint32_t b[4][2];
#pragma unroll
            for (int p = 0; p < 2; p++) {
                int row = n_w + p * 16 + b_row_l;
                ldsm_x4(swz_addr(bbase, row, ks * 2 + b_chk_l),
                        b[2 * p][0], b[2 * p][1], b[2 * p + 1][0], b[2 * p + 1][1]);
            }
#pragma unroll
            for (int mi = 0; mi < 4; mi++)
#pragma unroll
                for (int ni = 0; ni < 4; ni++)
                    mma_16816(c[mi][ni], a[mi], b[ni]);
        }
    }

    // ---- epilogue: fragment-direct float2 stores ----
    const int gm = i0 + m_w + (lane >> 2);
    const int gn = c0 + n_w + (lane & 3) * 2;
#pragma unroll
    for (int mi = 0; mi < 4; mi++) {
        size_t r0 = (size_t)(gm + mi * 16) * COLS_TOTAL + gn;
        size_t r1 = r0 + (size_t)8 * COLS_TOTAL;
#pragma unroll
        for (int ni = 0; ni < 4; ni++) {
            *(float2*)(out + r0 + ni * 8) = make_float2(c[mi][ni][0], c[mi][ni][1]);
            *(float2*)(out + r1 + ni * 8) = make_float2(c[mi][ni][2], c[mi][ni][3]);
        }
    }
}

// ============================================================================
// launch
// ============================================================================
extern "C" void kernel_launch(void* const* d_in, const int* in_sizes, int n_in,
                              void* d_out, int out_size) {
    const float* A  = (const float*)d_in[0];   // (64, 64) diagonal
    const float* Bm = (const float*)d_in[1];   // (64, 128)
    const float* C  = (const float*)d_in[2];   // (128, 64)
    float* out = (float*)d_out;                // (4096, 128, 128) fp32

    cudaFuncSetAttribute(s4d_mma_kernel,
                         cudaFuncAttributeMaxDynamicSharedMemorySize, SMEM_TOTAL);

    s4d_prep_v<<<(L_LEN * NS + 255) / 256, 256>>>(A);
    s4d_prep_w<<<(COLS_TOTAL * NS + 255) / 256, 256>>>(C, Bm);

    dim3 grid(COLS_TOTAL / 128, L_LEN / 128);  // (128, 32)
    s4d_mma_kernel<<<grid, 256, SMEM_TOTAL>>>(out);
}

// round 3
// speedup vs baseline: 1.1887x; 1.1887x over previous
#include <cuda_runtime.h>
#include <cuda_bf16.h>
#include <cstdint>

// ============================================================================
// S4D: K[i] = C @ A^i @ B, A diagonal.
//   K[i][m][d] = sum_n C[m][n] * a_n^i * B[n][d]
//   => GEMM: K[4096, 16384] = V[4096, 64] @ W[64, 16384]
//      V[i][n] = a_n^i,  W[n][m*128+d] = C[m][n]*B[n][d]
// Harness PTX target is sm_103 (generic) -> no tcgen05. mma.sync bf16 (HMMA)
// with bf16x3 error-compensated split (hi*hi + hi*lo + lo*hi).
// ============================================================================

#define L_LEN 4096
#define NS 64
#define DM 128
#define COLS_TOTAL (DM * DM)   // 16384

// -------- scratch (device globals: no allocation allowed) --------
__device__ __nv_bfloat16 g_Vhi[L_LEN * NS];
__device__ __nv_bfloat16 g_Vlo[L_LEN * NS];
__device__ __nv_bfloat16 g_Whi[COLS_TOTAL * NS];
__device__ __nv_bfloat16 g_Wlo[COLS_TOTAL * NS];
__device__ double g_l2a[NS];

// -------- SMEM layout: 4 tiles of 128 rows x 64 bf16 (128B rows, swizzled) --
#define SM_A_HI 0
#define SM_A_LO 16384
#define SM_B_HI 32768
#define SM_B_LO 49152
#define SMEM_TOTAL 65536

__device__ __forceinline__ uint32_t smem_u32(const void* p) {
    uint32_t a;
    asm("{ .reg .u64 t; cvta.to.shared.u64 t, %1; cvt.u32.u64 %0, t; }"
        : "=r"(a) : "l"(p));
    return a;
}

// row-XOR swizzle: 16B chunk c -> c ^ (row & 7). Conflict-free fills + LDSM.
__device__ __forceinline__ uint32_t swz_addr(uint32_t base, int row, int chunk) {
    return base + (uint32_t)row * 128u + (uint32_t)((chunk ^ (row & 7)) * 16);
}

__device__ __forceinline__ void ldsm_x4(uint32_t addr, uint32_t& r0, uint32_t& r1,
                                        uint32_t& r2, uint32_t& r3) {
    asm volatile("ldmatrix.sync.aligned.m8n8.x4.shared.b16 {%0,%1,%2,%3}, [%4];"
                 : "=r"(r0), "=r"(r1), "=r"(r2), "=r"(r3) : "r"(addr));
}

__device__ __forceinline__ void mma_16816(float* c, const uint32_t* a,
                                          const uint32_t* b) {
    asm volatile(
        "mma.sync.aligned.m16n8k16.row.col.f32.bf16.bf16.f32 "
        "{%0,%1,%2,%3}, {%4,%5,%6,%7}, {%8,%9}, {%0,%1,%2,%3};"
        : "+f"(c[0]), "+f"(c[1]), "+f"(c[2]), "+f"(c[3])
        : "r"(a[0]), "r"(a[1]), "r"(a[2]), "r"(a[3]), "r"(b[0]), "r"(b[1]));
}

// ============================================================================
// Prep 0: log2 of the diagonal, fp64, once per n (64 threads).
// ============================================================================
__global__ void s4d_prep_log(const float* __restrict__ A) {
    int n = threadIdx.x;
    if (n < NS) {
        float a = A[n * NS + n];
        g_l2a[n] = (a > 0.0f) ? log2((double)a) : -1.0e30;
    }
}

// ============================================================================
// Prep 1: V[i][n] = a_n^i = 2^(i*l2a[n]) via one fp64 mul + exp2f/ldexpf.
// Two n's per thread, bfloat162 stores.
// ============================================================================
__global__ void s4d_prep_v() {
    int idx = blockIdx.x * blockDim.x + threadIdx.x;   // over L_LEN * 32
    if (idx >= L_LEN * 32) return;
    int i  = idx >> 5;
    int n0 = (idx & 31) * 2;

    float v[2];
#pragma unroll
    for (int j = 0; j < 2; j++) {
        double e = (double)i * g_l2a[n0 + j];
        if (e < -200.0) {
            v[j] = 0.0f;
        } else {
            double fl = floor(e);
            v[j] = ldexpf(exp2f((float)(e - fl)), (int)fl);
        }
    }
    __nv_bfloat16 h0 = __float2bfloat16(v[0]);
    __nv_bfloat16 h1 = __float2bfloat16(v[1]);
    __nv_bfloat16 l0 = __float2bfloat16(v[0] - __bfloat162float(h0));
    __nv_bfloat16 l1 = __float2bfloat16(v[1] - __bfloat162float(h1));
    ((__nv_bfloat162*)g_Vhi)[idx] = __nv_bfloat162(h0, h1);
    ((__nv_bfloat162*)g_Vlo)[idx] = __nv_bfloat162(l0, l1);
}

// ============================================================================
// Prep 2: W[col][n] = C[m][n]*B[n][d], col = m*128+d. Two n's per thread.
// ============================================================================
__global__ void s4d_prep_w(const float* __restrict__ C, const float* __restrict__ Bm) {
    int idx = blockIdx.x * blockDim.x + threadIdx.x;   // over COLS_TOTAL * 32
    if (idx >= COLS_TOTAL * 32) return;
    int col = idx >> 5;
    int n0  = (idx & 31) * 2;
    int m = col >> 7;
    int d = col & 127;
    float w0 = C[m * NS + n0]     * Bm[n0 * DM + d];
    float w1 = C[m * NS + n0 + 1] * Bm[(n0 + 1) * DM + d];
    __nv_bfloat16 h0 = __float2bfloat16(w0);
    __nv_bfloat16 h1 = __float2bfloat16(w1);
    __nv_bfloat16 l0 = __float2bfloat16(w0 - __bfloat162float(h0));
    __nv_bfloat16 l1 = __float2bfloat16(w1 - __bfloat162float(h1));
    ((__nv_bfloat162*)g_Whi)[idx] = __nv_bfloat162(h0, h1);
    ((__nv_bfloat162*)g_Wlo)[idx] = __nv_bfloat162(l0, l1);
}

// ============================================================================
// Main: CTA = 128(i) x 128(col), 8 warps of 64x32.
// Phase 1: per k-step load Ahi once, MMA vs Bhi then Blo (A-frag reuse).
// Phase 2: per k-step load Alo, MMA vs Bhi.
// Epilogue: fragment-direct float2 stores (full 32B sectors).
// ============================================================================
__global__ void __launch_bounds__(256, 2) s4d_mma_kernel(float* __restrict__ out) {
    extern __shared__ char smem[];
    const uint32_t sb = smem_u32(smem);
    const int tid  = threadIdx.x;
    const int wid  = tid >> 5;
    const int lane = tid & 31;
    const int c0 = blockIdx.x * 128;   // output-column tile
    const int i0 = blockIdx.y * 128;   // i-row tile

    // ---- fill 4 SMEM tiles (each 128 rows x 8 x 16B chunks, swizzled) ----
    {
        const uint4* vhi = (const uint4*)g_Vhi;
        const uint4* vlo = (const uint4*)g_Vlo;
        const uint4* whi = (const uint4*)g_Whi;
        const uint4* wlo = (const uint4*)g_Wlo;
        uint4* s = (uint4*)smem;
#pragma unroll
        for (int j = 0; j < 4; j++) {
            int idx = tid + j * 256;          // 1024 chunks per tile
            int r  = idx >> 3;
            int ch = idx & 7;
            int cs = ch ^ (r & 7);
            int so = r * 8 + cs;
            s[(SM_A_HI >> 4) + so] = vhi[(size_t)(i0 + r) * 8 + ch];
            s[(SM_A_LO >> 4) + so] = vlo[(size_t)(i0 + r) * 8 + ch];
            s[(SM_B_HI >> 4) + so] = whi[(size_t)(c0 + r) * 8 + ch];
            s[(SM_B_LO >> 4) + so] = wlo[(size_t)(c0 + r) * 8 + ch];
        }
    }
    __syncthreads();

    // ---- warp tiling: warp w covers rows m_w..m_w+63, cols n_w..n_w+31 ----
    const int m_w = (wid & 1) * 64;
    const int n_w = (wid >> 1) * 32;

    float c[4][4][4];
#pragma unroll
    for (int mi = 0; mi < 4; mi++)
#pragma unroll
        for (int ni = 0; ni < 4; ni++)
#pragma unroll
            for (int k = 0; k < 4; k++) c[mi][ni][k] = 0.0f;

    // ldmatrix row/chunk components (per lane, base-relative)
    const int a_row_l = (lane & 7) + ((lane >> 3) & 1) * 8;   // within 16-row tile
    const int a_chk_l = (lane >> 4);                          // 0 or 1
    const int b_row_l = (lane & 7) + ((lane >> 4) & 1) * 8;   // within 16-n pair
    const int b_chk_l = (lane >> 3) & 1;

    // ---- phase 1: Ahi * (Bhi, Blo) — A fragments loaded once per k-step ----
#pragma unroll
    for (int ks = 0; ks < 4; ks++) {
        uint32_t a[4][4];
#pragma unroll
        for (int mi = 0; mi < 4; mi++) {
            int row = m_w + mi * 16 + a_row_l;
            ldsm_x4(swz_addr(sb + SM_A_HI, row, ks * 2 + a_chk_l),
                    a[mi][0], a[mi][1], a[mi][2], a[mi][3]);
        }
        uint32_t b[4][2];
#pragma unroll
        for (int p = 0; p < 2; p++) {
            int row = n_w + p * 16 + b_row_l;
            ldsm_x4(swz_addr(sb + SM_B_HI, row, ks * 2 + b_chk_l),
                    b[2 * p][0], b[2 * p][1], b[2 * p + 1][0], b[2 * p + 1][1]);
        }
#pragma unroll
        for (int mi = 0; mi < 4; mi++)
#pragma unroll
            for (int ni = 0; ni < 4; ni++)
                mma_16816(c[mi][ni], a[mi], b[ni]);
        // B-lo with the same A fragments
#pragma unroll
        for (int p = 0; p < 2; p++) {
            int row = n_w + p * 16 + b_row_l;
            ldsm_x4(swz_addr(sb + SM_B_LO, row, ks * 2 + b_chk_l),
                    b[2 * p][0], b[2 * p][1], b[2 * p + 1][0], b[2 * p + 1][1]);
        }
#pragma unroll
        for (int mi = 0; mi < 4; mi++)
#pragma unroll
            for (int ni = 0; ni < 4; ni++)
                mma_16816(c[mi][ni], a[mi], b[ni]);
    }

    // ---- phase 2: Alo * Bhi ----
#pragma unroll
    for (int ks = 0; ks < 4; ks++) {
        uint32_t a[4][4];
#pragma unroll
        for (int mi = 0; mi < 4; mi++) {
            int row = m_w + mi * 16 + a_row_l;
            ldsm_x4(swz_addr(sb + SM_A_LO, row, ks * 2 + a_chk_l),
                    a[mi][0], a[mi][1], a[mi][2], a[mi][3]);
        }
        uint32_t b[4][2];
#pragma unroll
        for (int p = 0; p < 2; p++) {
            int row = n_w + p * 16 + b_row_l;
            ldsm_x4(swz_addr(sb + SM_B_HI, row, ks * 2 + b_chk_l),
                    b[2 * p][0], b[2 * p][1], b[2 * p + 1][0], b[2 * p + 1][1]);
        }
#pragma unroll
        for (int mi = 0; mi < 4; mi++)
#pragma unroll
            for (int ni = 0; ni < 4; ni++)
                mma_16816(c[mi][ni], a[mi], b[ni]);
    }

    // ---- epilogue: fragment-direct float2 stores ----
    const int gm = i0 + m_w + (lane >> 2);
    const int gn = c0 + n_w + (lane & 3) * 2;
#pragma unroll
    for (int mi = 0; mi < 4; mi++) {
        size_t r0 = (size_t)(gm + mi * 16) * COLS_TOTAL + gn;
        size_t r1 = r0 + (size_t)8 * COLS_TOTAL;
#pragma unroll
        for (int ni = 0; ni < 4; ni++) {
            *(float2*)(out + r0 + ni * 8) = make_float2(c[mi][ni][0], c[mi][ni][1]);
            *(float2*)(out + r1 + ni * 8) = make_float2(c[mi][ni][2], c[mi][ni][3]);
        }
    }
}

// ============================================================================
// launch
// ============================================================================
extern "C" void kernel_launch(void* const* d_in, const int* in_sizes, int n_in,
                              void* d_out, int out_size) {
    const float* A  = (const float*)d_in[0];   // (64, 64) diagonal
    const float* Bm = (const float*)d_in[1];   // (64, 128)
    const float* C  = (const float*)d_in[2];   // (128, 64)
    float* out = (float*)d_out;                // (4096, 128, 128) fp32

    cudaFuncSetAttribute(s4d_mma_kernel,
                         cudaFuncAttributeMaxDynamicSharedMemorySize, SMEM_TOTAL);

    s4d_prep_log<<<1, 64>>>(A);
    s4d_prep_v<<<(L_LEN * 32 + 255) / 256, 256>>>();
    s4d_prep_w<<<(COLS_TOTAL * 32 + 255) / 256, 256>>>(C, Bm);

    dim3 grid(COLS_TOTAL / 128, L_LEN / 128);  // (128, 32)
    s4d_mma_kernel<<<grid, 256, SMEM_TOTAL>>>(out);
}

// round 4
// speedup vs baseline: 1.4003x; 1.1780x over previous
#include <cuda_runtime.h>
#include <cuda_bf16.h>
#include <cstdint>

// ============================================================================
// S4D: K[i] = C @ A^i @ B, A diagonal.
//   K[i][m][d] = sum_n C[m][n] * a_n^i * B[n][d]
//   => GEMM: K[4096, 16384] = V[4096, 64] @ W[64, 16384]
//      V[i][n] = a_n^i,  W[n][m*128+d] = C[m][n]*B[n][d]
// sm_103 generic target -> mma.sync bf16 (HMMA), bf16x3 split.
// R4: operands stored in mma.sync FRAGMENT ORDER in gmem -> direct LDG.128
// into fragments. No SMEM, no STS, no LDSM: L1 traffic 416KB -> 160KB/CTA.
// ============================================================================

#define L_LEN 4096
#define NS 64
#define DM 128
#define COLS_TOTAL (DM * DM)   // 16384

// A-fragment array: [strip(32) x blk(8)][ks(4)][lane(32)] uint4 (a0..a3)
//   element (strip*8+blk, ks, lane): rows r0 = (strip*8+blk)*16 + lane/4,
//   r1 = r0+8; n = ks*16 + (lane%4)*2 (+1, +8, +9)
#define VF_ELEMS (256 * 4 * 32)          // 32768
// B-fragment array: [ct(128) x nb(16)][ks(4)][lane(32)] uint2 (b0, b1)
//   col = (ct*16+nb)*8 + lane/4; k = ks*16 + (lane%4)*2 (+1, +8, +9)
#define WF_ELEMS (2048 * 4 * 32)         // 262144

__device__ uint4 g_VFhi[VF_ELEMS];
__device__ uint4 g_VFlo[VF_ELEMS];
__device__ uint2 g_WFhi[WF_ELEMS];
__device__ uint2 g_WFlo[WF_ELEMS];
__device__ double g_l2a[NS];

__device__ __forceinline__ void mma_16816(float* c, const uint32_t* a,
                                          const uint32_t* b) {
    asm volatile(
        "mma.sync.aligned.m16n8k16.row.col.f32.bf16.bf16.f32 "
        "{%0,%1,%2,%3}, {%4,%5,%6,%7}, {%8,%9}, {%0,%1,%2,%3};"
        : "+f"(c[0]), "+f"(c[1]), "+f"(c[2]), "+f"(c[3])
        : "r"(a[0]), "r"(a[1]), "r"(a[2]), "r"(a[3]), "r"(b[0]), "r"(b[1]));
}

__device__ __forceinline__ uint32_t pack_bf2(__nv_bfloat16 x, __nv_bfloat16 y) {
    __nv_bfloat162 t(x, y);           // .x = low 16 bits
    return *(uint32_t*)&t;
}

// split float pair into packed bf16 hi and lo words
__device__ __forceinline__ void split2(float v0, float v1,
                                       uint32_t& hi, uint32_t& lo) {
    __nv_bfloat16 h0 = __float2bfloat16(v0);
    __nv_bfloat16 h1 = __float2bfloat16(v1);
    float l0 = v0 - __bfloat162float(h0);
    float l1 = v1 - __bfloat162float(h1);
    hi = pack_bf2(h0, h1);
    lo = pack_bf2(__float2bfloat16(l0), __float2bfloat16(l1));
}

// ============================================================================
// Prep 0: log2 of the diagonal in fp64 (64 threads).
// ============================================================================
__global__ void s4d_prep_log(const float* __restrict__ A) {
    int n = threadIdx.x;
    if (n < NS) {
        float a = A[n * NS + n];
        g_l2a[n] = (a > 0.0f) ? log2((double)a) : -1.0e30;
    }
}

// v(i, n) = a_n^i = 2^(i * l2a[n]) : one fp64 mul + exp2f + ldexpf
__device__ __forceinline__ float pow_in(int i, double l2) {
    double e = (double)i * l2;
    if (e < -200.0) return 0.0f;
    double fl = floor(e);
    return ldexpf(exp2f((float)(e - fl)), (int)fl);
}

// ============================================================================
// Prep 1: V in A-fragment order. One uint4 (hi) + uint4 (lo) per thread.
// ============================================================================
__global__ void s4d_prep_vf() {
    int idx = blockIdx.x * blockDim.x + threadIdx.x;
    if (idx >= VF_ELEMS) return;
    int lane = idx & 31;
    int ks   = (idx >> 5) & 3;
    int blkf = idx >> 7;                 // strip*8 + blk
    int g  = lane >> 2;
    int tg = lane & 3;
    int r0 = blkf * 16 + g;
    int r1 = r0 + 8;
    int k0 = ks * 16 + tg * 2;

    double l2_0 = g_l2a[k0],     l2_1 = g_l2a[k0 + 1];
    double l2_8 = g_l2a[k0 + 8], l2_9 = g_l2a[k0 + 9];

    uint4 hi, lo;
    split2(pow_in(r0, l2_0), pow_in(r0, l2_1), hi.x, lo.x);   // a0
    split2(pow_in(r1, l2_0), pow_in(r1, l2_1), hi.y, lo.y);   // a1
    split2(pow_in(r0, l2_8), pow_in(r0, l2_9), hi.z, lo.z);   // a2
    split2(pow_in(r1, l2_8), pow_in(r1, l2_9), hi.w, lo.w);   // a3
    g_VFhi[idx] = hi;
    g_VFlo[idx] = lo;
}

// ============================================================================
// Prep 2: W in B-fragment order. One uint2 (hi) + uint2 (lo) per thread.
// ============================================================================
__global__ void s4d_prep_wf(const float* __restrict__ C, const float* __restrict__ Bm) {
    int idx = blockIdx.x * blockDim.x + threadIdx.x;
    if (idx >= WF_ELEMS) return;
    int lane = idx & 31;
    int ks   = (idx >> 5) & 3;
    int nbf  = idx >> 7;                 // ct*16 + nb
    int g  = lane >> 2;
    int tg = lane & 3;
    int col = nbf * 8 + g;
    int k0  = ks * 16 + tg * 2;
    int m = col >> 7;
    int d = col & 127;

    const float* Crow = C + m * NS;
    float w0 = Crow[k0]     * Bm[k0 * DM + d];
    float w1 = Crow[k0 + 1] * Bm[(k0 + 1) * DM + d];
    float w8 = Crow[k0 + 8] * Bm[(k0 + 8) * DM + d];
    float w9 = Crow[k0 + 9] * Bm[(k0 + 9) * DM + d];

    uint2 hi, lo;
    split2(w0, w1, hi.x, lo.x);          // b0
    split2(w8, w9, hi.y, lo.y);          // b1
    g_WFhi[idx] = hi;
    g_WFlo[idx] = lo;
}

// ============================================================================
// Main: CTA = 128(i) x 128(col), 8 warps of 64x32. No SMEM. Fragments loaded
// directly with LDG.128/LDG.64 from fragment-order arrays.
// Per k-step: Ahi*(Bhi,Blo) then Alo*Bhi.
// ============================================================================
__global__ void __launch_bounds__(256, 2) s4d_mma_kernel(float* __restrict__ out) {
    const int tid  = threadIdx.x;
    const int wid  = tid >> 5;
    const int lane = tid & 31;
    const int m_w = (wid & 1) * 64;
    const int n_w = (wid >> 1) * 32;

    // fragment base indices (element granularity)
    // A: ((strip*8 + m_w/16 + mi)*4 + ks)*32 + lane
    const int abase = ((blockIdx.y * 8 + (m_w >> 4)) * 4) * 32 + lane;
    // B: ((ct*16 + n_w/8 + ni)*4 + ks)*32 + lane
    const int bbase = ((blockIdx.x * 16 + (n_w >> 3)) * 4) * 32 + lane;

    float c[4][4][4];
#pragma unroll
    for (int mi = 0; mi < 4; mi++)
#pragma unroll
        for (int ni = 0; ni < 4; ni++)
#pragma unroll
            for (int k = 0; k < 4; k++) c[mi][ni][k] = 0.0f;

#pragma unroll
    for (int ks = 0; ks < 4; ks++) {
        uint4 ahi[4];
        uint2 bhi[4], blo[4];
#pragma unroll
        for (int mi = 0; mi < 4; mi++) ahi[mi] = g_VFhi[abase + mi * 128 + ks * 32];
#pragma unroll
        for (int ni = 0; ni < 4; ni++) bhi[ni] = g_WFhi[bbase + ni * 128 + ks * 32];
#pragma unroll
        for (int ni = 0; ni < 4; ni++) blo[ni] = g_WFlo[bbase + ni * 128 + ks * 32];

#pragma unroll
        for (int mi = 0; mi < 4; mi++)
#pragma unroll
            for (int ni = 0; ni < 4; ni++)
                mma_16816(c[mi][ni], (const uint32_t*)&ahi[mi],
                          (const uint32_t*)&bhi[ni]);
#pragma unroll
        for (int mi = 0; mi < 4; mi++)
#pragma unroll
            for (int ni = 0; ni < 4; ni++)
                mma_16816(c[mi][ni], (const uint32_t*)&ahi[mi],
                          (const uint32_t*)&blo[ni]);

        uint4 alo[4];
#pragma unroll
        for (int mi = 0; mi < 4; mi++) alo[mi] = g_VFlo[abase + mi * 128 + ks * 32];
#pragma unroll
        for (int mi = 0; mi < 4; mi++)
#pragma unroll
            for (int ni = 0; ni < 4; ni++)
                mma_16816(c[mi][ni], (const uint32_t*)&alo[mi],
                          (const uint32_t*)&bhi[ni]);
    }

    // ---- epilogue: fragment-direct float2 stores (full 128B lines) ----
    const int gm = blockIdx.y * 128 + m_w + (lane >> 2);
    const int gn = blockIdx.x * 128 + n_w + (lane & 3) * 2;
#pragma unroll
    for (int mi = 0; mi < 4; mi++) {
        size_t r0 = (size_t)(gm + mi * 16) * COLS_TOTAL + gn;
        size_t r1 = r0 + (size_t)8 * COLS_TOTAL;
#pragma unroll
        for (int ni = 0; ni < 4; ni++) {
            *(float2*)(out + r0 + ni * 8) = make_float2(c[mi][ni][0], c[mi][ni][1]);
            *(float2*)(out + r1 + ni * 8) = make_float2(c[mi][ni][2], c[mi][ni][3]);
        }
    }
}

// ============================================================================
// launch
// ============================================================================
extern "C" void kernel_launch(void* const* d_in, const int* in_sizes, int n_in,
                              void* d_out, int out_size) {
    const float* A  = (const float*)d_in[0];   // (64, 64) diagonal
    const float* Bm = (const float*)d_in[1];   // (64, 128)
    const float* C  = (const float*)d_in[2];   // (128, 64)
    float* out = (float*)d_out;                // (4096, 128, 128) fp32

    s4d_prep_log<<<1, 64>>>(A);
    s4d_prep_vf<<<VF_ELEMS / 256, 256>>>();
    s4d_prep_wf<<<WF_ELEMS / 256, 256>>>(C, Bm);

    dim3 grid(COLS_TOTAL / 128, L_LEN / 128);  // (128, 32)
    s4d_mma_kernel<<<grid, 256>>>(out);
}